// round 3
// baseline (speedup 1.0000x reference)
#include <cuda_runtime.h>

// OpenLSTM: B=4096 sequences, T=1024, HID=16, PROJ=2.
// t < 256 teacher-forced; t >= 256 recurrent.
//
// R3: 2 independent elements per thread (dual-stream) to hide the per-step
// dependency chain (gates->TANH->c->TANH->proj->3xSHFL ~150cyc) that left
// issue at 30% with single-stream. Weights shared across both streams.
// Layout: 8 lanes per element-pair-group, 2 hidden units per lane per element,
// 4 groups/warp -> 8 elements/warp, 512 blocks x 32 threads.

#define T_TOTAL 1024
#define N_CTX   256
#define TPE     8
#define EPT     2     // elements per thread
#define EPW     8     // elements per warp (4 groups x 2)

__device__ __forceinline__ float tanh_fast(float x) {
    float y;
    asm("tanh.approx.f32 %0, %1;" : "=f"(y) : "f"(x));
    return y;
}
__device__ __forceinline__ float sigmoid_fast(float x) {
    return fmaf(tanh_fast(0.5f * x), 0.5f, 0.5f);
}

__global__ void __launch_bounds__(32)
open_lstm_kernel(const float* __restrict__ u,     // (B, T, 4)
                 const float* __restrict__ w_ih,  // (64, 2)
                 const float* __restrict__ w_hh,  // (64, 2)
                 const float* __restrict__ b_ih,  // (64)
                 const float* __restrict__ b_hh,  // (64)
                 const float* __restrict__ w_hr,  // (2, 16)
                 float* __restrict__ out)         // (B, T, 2)
{
    const int lane = threadIdx.x;
    const int g    = lane & (TPE - 1);       // 0..7: unit-slot within group
    const int grp  = lane >> 3;              // 0..3: group within warp
    const int e0   = blockIdx.x * EPW + grp * EPT;   // this thread's elements: e0, e0+1

    // Weights: shared across both element streams. Units j = g, g+8; gates i,f,g,o.
    float wi[2][4][2], wh[2][4][2], bb[2][4], wr0[2], wr1[2];
#pragma unroll
    for (int uu = 0; uu < 2; uu++) {
        int j = g + uu * 8;
#pragma unroll
        for (int k = 0; k < 4; k++) {
            int r = k * 16 + j;
            wi[uu][k][0] = w_ih[r * 2 + 0];
            wi[uu][k][1] = w_ih[r * 2 + 1];
            wh[uu][k][0] = w_hh[r * 2 + 0];
            wh[uu][k][1] = w_hh[r * 2 + 1];
            bb[uu][k]    = b_ih[r] + b_hh[r];
        }
        wr0[uu] = w_hr[j];
        wr1[uu] = w_hr[16 + j];
    }

    const float4* __restrict__ up[EPT];
    float2* __restrict__ op[EPT];
#pragma unroll
    for (int ee = 0; ee < EPT; ee++) {
        up[ee] = (const float4*)u + (size_t)(e0 + ee) * T_TOTAL;
        op[ee] = (float2*)out + (size_t)(e0 + ee) * T_TOTAL;
    }

    float c[EPT][2];
    float h0[EPT], h1[EPT];
    float xp[EPT][2][4];
    float4 v[EPT];

#pragma unroll
    for (int ee = 0; ee < EPT; ee++) {
        c[ee][0] = c[ee][1] = 0.0f;
        h0[ee] = h1[ee] = 0.0f;
        v[ee] = up[ee][0];
#pragma unroll
        for (int uu = 0; uu < 2; uu++)
#pragma unroll
            for (int k = 0; k < 4; k++)
                xp[ee][uu][k] = fmaf(wi[uu][k][0], v[ee].x,
                                fmaf(wi[uu][k][1], v[ee].y, bb[uu][k]));
    }

    // ---------------- teacher-forced phase ----------------
#pragma unroll 1
    for (int t = 0; t < N_CTX; t++) {
        float4 vn[EPT];
#pragma unroll
        for (int ee = 0; ee < EPT; ee++) vn[ee] = up[ee][t + 1];

        float p0[EPT], p1[EPT];
#pragma unroll
        for (int ee = 0; ee < EPT; ee++) {
            const float hi0 = v[ee].z, hi1 = v[ee].w;
            p0[ee] = 0.0f; p1[ee] = 0.0f;
#pragma unroll
            for (int uu = 0; uu < 2; uu++) {
                float gi = fmaf(wh[uu][0][0], hi0, fmaf(wh[uu][0][1], hi1, xp[ee][uu][0]));
                float gf = fmaf(wh[uu][1][0], hi0, fmaf(wh[uu][1][1], hi1, xp[ee][uu][1]));
                float gg = fmaf(wh[uu][2][0], hi0, fmaf(wh[uu][2][1], hi1, xp[ee][uu][2]));
                float go = fmaf(wh[uu][3][0], hi0, fmaf(wh[uu][3][1], hi1, xp[ee][uu][3]));

                float si = sigmoid_fast(gi);
                float sf = sigmoid_fast(gf);
                float tg = tanh_fast(gg);
                float so = sigmoid_fast(go);

                c[ee][uu] = fmaf(sf, c[ee][uu], si * tg);
                float s = so * tanh_fast(c[ee][uu]);

                p0[ee] = fmaf(wr0[uu], s, p0[ee]);
                p1[ee] = fmaf(wr1[uu], s, p1[ee]);
            }
        }
        // interleaved butterfly reductions for both streams
#pragma unroll
        for (int k = 1; k < TPE; k <<= 1) {
#pragma unroll
            for (int ee = 0; ee < EPT; ee++) {
                p0[ee] += __shfl_xor_sync(0xffffffffu, p0[ee], k, TPE);
                p1[ee] += __shfl_xor_sync(0xffffffffu, p1[ee], k, TPE);
            }
        }
#pragma unroll
        for (int ee = 0; ee < EPT; ee++) {
            h0[ee] = p0[ee]; h1[ee] = p1[ee];
            if (g == 0) op[ee][t] = make_float2(p0[ee], p1[ee]);
            // next step's x-part (independent filler)
#pragma unroll
            for (int uu = 0; uu < 2; uu++)
#pragma unroll
                for (int k = 0; k < 4; k++)
                    xp[ee][uu][k] = fmaf(wi[uu][k][0], vn[ee].x,
                                    fmaf(wi[uu][k][1], vn[ee].y, bb[uu][k]));
            v[ee] = vn[ee];
        }
    }

    // ---------------- recurrent phase ----------------
#pragma unroll 1
    for (int t = N_CTX; t < T_TOTAL; t++) {
        const int tn = (t + 1 < T_TOTAL) ? (t + 1) : t;
        float4 vn[EPT];
#pragma unroll
        for (int ee = 0; ee < EPT; ee++) vn[ee] = up[ee][tn];

        float p0[EPT], p1[EPT];
#pragma unroll
        for (int ee = 0; ee < EPT; ee++) {
            const float hi0 = h0[ee], hi1 = h1[ee];
            p0[ee] = 0.0f; p1[ee] = 0.0f;
#pragma unroll
            for (int uu = 0; uu < 2; uu++) {
                float gi = fmaf(wh[uu][0][0], hi0, fmaf(wh[uu][0][1], hi1, xp[ee][uu][0]));
                float gf = fmaf(wh[uu][1][0], hi0, fmaf(wh[uu][1][1], hi1, xp[ee][uu][1]));
                float gg = fmaf(wh[uu][2][0], hi0, fmaf(wh[uu][2][1], hi1, xp[ee][uu][2]));
                float go = fmaf(wh[uu][3][0], hi0, fmaf(wh[uu][3][1], hi1, xp[ee][uu][3]));

                float si = sigmoid_fast(gi);
                float sf = sigmoid_fast(gf);
                float tg = tanh_fast(gg);
                float so = sigmoid_fast(go);

                c[ee][uu] = fmaf(sf, c[ee][uu], si * tg);
                float s = so * tanh_fast(c[ee][uu]);

                p0[ee] = fmaf(wr0[uu], s, p0[ee]);
                p1[ee] = fmaf(wr1[uu], s, p1[ee]);
            }
        }
#pragma unroll
        for (int k = 1; k < TPE; k <<= 1) {
#pragma unroll
            for (int ee = 0; ee < EPT; ee++) {
                p0[ee] += __shfl_xor_sync(0xffffffffu, p0[ee], k, TPE);
                p1[ee] += __shfl_xor_sync(0xffffffffu, p1[ee], k, TPE);
            }
        }
#pragma unroll
        for (int ee = 0; ee < EPT; ee++) {
            h0[ee] = p0[ee]; h1[ee] = p1[ee];
            if (g == 0) op[ee][t] = make_float2(p0[ee], p1[ee]);
#pragma unroll
            for (int uu = 0; uu < 2; uu++)
#pragma unroll
                for (int k = 0; k < 4; k++)
                    xp[ee][uu][k] = fmaf(wi[uu][k][0], vn[ee].x,
                                    fmaf(wi[uu][k][1], vn[ee].y, bb[uu][k]));
            v[ee] = vn[ee];
        }
    }
}

extern "C" void kernel_launch(void* const* d_in, const int* in_sizes, int n_in,
                              void* d_out, int out_size)
{
    const float* u    = (const float*)d_in[0];
    const float* w_ih = (const float*)d_in[1];
    const float* w_hh = (const float*)d_in[2];
    const float* b_ih = (const float*)d_in[3];
    const float* b_hh = (const float*)d_in[4];
    const float* w_hr = (const float*)d_in[5];
    float* out = (float*)d_out;

    const int B = in_sizes[0] / (T_TOTAL * 4);   // 4096
    const int grid = B / EPW;                    // 512 blocks x 32 threads

    open_lstm_kernel<<<grid, 32>>>(u, w_ih, w_hh, b_ih, b_hh, w_hr, out);
}

// round 4
// speedup vs baseline: 1.3299x; 1.3299x over previous
#include <cuda_runtime.h>

// OpenLSTM: B=4096 sequences, T=1024, HID=16, PROJ=2.
// t < 256 teacher-forced; t >= 256 recurrent.
//
// R4: TPE=16 (1 hidden unit per thread, 2 elements per warp) -> 2048 warps
// (3.46/SMSP) for latency hiding; R3 showed warp count beats per-warp ILP.
// Sigmoid scaling folded into weights (i/f/o rows pre-scaled by 0.5, w_hr
// pre-scaled by 0.5) so each activation is a bare MUFU.TANH.

#define T_TOTAL 1024
#define N_CTX   256
#define TPE     16    // threads per element
#define EPB     4     // elements per 64-thread block

__device__ __forceinline__ float tanh_fast(float x) {
    float y;
    asm("tanh.approx.f32 %0, %1;" : "=f"(y) : "f"(x));
    return y;
}

__global__ void __launch_bounds__(64)
open_lstm_kernel(const float* __restrict__ u,     // (B, T, 4)
                 const float* __restrict__ w_ih,  // (64, 2)
                 const float* __restrict__ w_hh,  // (64, 2)
                 const float* __restrict__ b_ih,  // (64)
                 const float* __restrict__ b_hh,  // (64)
                 const float* __restrict__ w_hr,  // (2, 16)
                 float* __restrict__ out)         // (B, T, 2)
{
    const int tid  = threadIdx.x;
    const int j    = tid & (TPE - 1);                 // hidden unit 0..15
    const int e    = blockIdx.x * EPB + (tid >> 4);   // element index

    // Per-thread weights for unit j, gates k = i,f,g,o.
    // Fold sigma(x) = 0.5*tanh(0.5x)+0.5: scale i/f/o gate rows by 0.5.
    // Fold the o-gate's outer 0.5 into w_hr.
    float wi[4][2], wh[4][2], bb[4], wr0, wr1;
#pragma unroll
    for (int k = 0; k < 4; k++) {
        const int r = k * 16 + j;
        const float sc = (k == 2) ? 1.0f : 0.5f;      // g gate unscaled
        wi[k][0] = w_ih[r * 2 + 0] * sc;
        wi[k][1] = w_ih[r * 2 + 1] * sc;
        wh[k][0] = w_hh[r * 2 + 0] * sc;
        wh[k][1] = w_hh[r * 2 + 1] * sc;
        bb[k]    = (b_ih[r] + b_hh[r]) * sc;
    }
    wr0 = w_hr[j]      * 0.5f;
    wr1 = w_hr[16 + j] * 0.5f;

    const float4* __restrict__ up = (const float4*)u + (size_t)e * T_TOTAL;
    float2* __restrict__ op       = (float2*)out + (size_t)e * T_TOTAL;

    float c = 0.0f, h0 = 0.0f, h1 = 0.0f;

    float4 v = up[0];
    float xp[4];
#pragma unroll
    for (int k = 0; k < 4; k++)
        xp[k] = fmaf(wi[k][0], v.x, fmaf(wi[k][1], v.y, bb[k]));

    // ---------------- teacher-forced phase (h input from data) ----------------
#pragma unroll 2
    for (int t = 0; t < N_CTX; t++) {
        float4 vn = up[t + 1];
        const float hi0 = v.z, hi1 = v.w;

        float gi = fmaf(wh[0][0], hi0, fmaf(wh[0][1], hi1, xp[0]));
        float gf = fmaf(wh[1][0], hi0, fmaf(wh[1][1], hi1, xp[1]));
        float gg = fmaf(wh[2][0], hi0, fmaf(wh[2][1], hi1, xp[2]));
        float go = fmaf(wh[3][0], hi0, fmaf(wh[3][1], hi1, xp[3]));

        float ti = tanh_fast(gi);
        float tf = tanh_fast(gf);
        float tg = tanh_fast(gg);
        float to = tanh_fast(go);

        // c = sigma(f)*c + sigma(i)*tanh(g), sigmas expanded with 0.5 folding
        float ca = fmaf(tf, c, c);           // 2*sigma(f)*c
        float cb = fmaf(ti, tg, tg);         // 2*sigma(i)*tanh(g)
        c = fmaf(0.5f, ca, 0.5f * cb);

        float tc = tanh_fast(c);
        float s  = fmaf(to, tc, tc);         // 2*sigma(o)*tanh(c); 0.5 in wr

        float p0 = wr0 * s;
        float p1 = wr1 * s;
#pragma unroll
        for (int k = 1; k < TPE; k <<= 1) {
            p0 += __shfl_xor_sync(0xffffffffu, p0, k, TPE);
            p1 += __shfl_xor_sync(0xffffffffu, p1, k, TPE);
        }
        h0 = p0; h1 = p1;
        if (j == 0) op[t] = make_float2(p0, p1);

        // next step's x-part (off critical chain)
#pragma unroll
        for (int k = 0; k < 4; k++)
            xp[k] = fmaf(wi[k][0], vn.x, fmaf(wi[k][1], vn.y, bb[k]));
        v = vn;
    }

    // ---------------- recurrent phase (h feeds back) ---------------------------
#pragma unroll 1
    for (int t = N_CTX; t < T_TOTAL; t++) {
        float4 vn = up[(t + 1 < T_TOTAL) ? (t + 1) : t];
        const float hi0 = h0, hi1 = h1;

        float gi = fmaf(wh[0][0], hi0, fmaf(wh[0][1], hi1, xp[0]));
        float gf = fmaf(wh[1][0], hi0, fmaf(wh[1][1], hi1, xp[1]));
        float gg = fmaf(wh[2][0], hi0, fmaf(wh[2][1], hi1, xp[2]));
        float go = fmaf(wh[3][0], hi0, fmaf(wh[3][1], hi1, xp[3]));

        float ti = tanh_fast(gi);
        float tf = tanh_fast(gf);
        float tg = tanh_fast(gg);
        float to = tanh_fast(go);

        float ca = fmaf(tf, c, c);
        float cb = fmaf(ti, tg, tg);
        c = fmaf(0.5f, ca, 0.5f * cb);

        float tc = tanh_fast(c);
        float s  = fmaf(to, tc, tc);

        float p0 = wr0 * s;
        float p1 = wr1 * s;
#pragma unroll
        for (int k = 1; k < TPE; k <<= 1) {
            p0 += __shfl_xor_sync(0xffffffffu, p0, k, TPE);
            p1 += __shfl_xor_sync(0xffffffffu, p1, k, TPE);
        }
        h0 = p0; h1 = p1;
        if (j == 0) op[t] = make_float2(p0, p1);

#pragma unroll
        for (int k = 0; k < 4; k++)
            xp[k] = fmaf(wi[k][0], vn.x, fmaf(wi[k][1], vn.y, bb[k]));
        v = vn;
    }
}

extern "C" void kernel_launch(void* const* d_in, const int* in_sizes, int n_in,
                              void* d_out, int out_size)
{
    const float* u    = (const float*)d_in[0];
    const float* w_ih = (const float*)d_in[1];
    const float* w_hh = (const float*)d_in[2];
    const float* b_ih = (const float*)d_in[3];
    const float* b_hh = (const float*)d_in[4];
    const float* w_hr = (const float*)d_in[5];
    float* out = (float*)d_out;

    const int B = in_sizes[0] / (T_TOTAL * 4);   // 4096
    const int grid = B / EPB;                    // 1024 blocks x 64 threads

    open_lstm_kernel<<<grid, 64>>>(u, w_ih, w_hh, b_ih, b_hh, w_hr, out);
}

// round 5
// speedup vs baseline: 1.5109x; 1.1362x over previous
#include <cuda_runtime.h>

// OpenLSTM: B=4096 sequences, T=1024, HID=16, PROJ=2.
// t < 256 teacher-forced; t >= 256 recurrent.
//
// R5: teacher phase unrolled x4 with batched independent work (16 gate-TANHs,
// 4 shuffle trees, 4 stores per iter all independent; only the 8-cyc c-FMA
// chain is serial) -> teacher runs at throughput floor instead of paying the
// ~410-cyc recurrent-style per-step latency. Recurrent loop kept identical to
// R4 (217us) for clean attribution.
// Layout: TPE=16 (1 unit/thread, 2 elements/warp), 2048 warps.

#define T_TOTAL 1024
#define N_CTX   256
#define TPE     16
#define EPB     4     // elements per 64-thread block
#define TU      4     // teacher-phase time unroll

__device__ __forceinline__ float tanh_fast(float x) {
    float y;
    asm("tanh.approx.f32 %0, %1;" : "=f"(y) : "f"(x));
    return y;
}

__global__ void __launch_bounds__(64)
open_lstm_kernel(const float* __restrict__ u,     // (B, T, 4)
                 const float* __restrict__ w_ih,  // (64, 2)
                 const float* __restrict__ w_hh,  // (64, 2)
                 const float* __restrict__ b_ih,  // (64)
                 const float* __restrict__ b_hh,  // (64)
                 const float* __restrict__ w_hr,  // (2, 16)
                 float* __restrict__ out)         // (B, T, 2)
{
    const int tid  = threadIdx.x;
    const int j    = tid & (TPE - 1);                 // hidden unit 0..15
    const int e    = blockIdx.x * EPB + (tid >> 4);   // element index

    // Per-thread weights for unit j. sigma(x)=0.5*tanh(0.5x)+0.5 folded:
    // i/f/o gate rows pre-scaled by 0.5; o-path outer 0.5 folded into w_hr.
    float wi[4][2], wh[4][2], bb[4], wr0, wr1;
#pragma unroll
    for (int k = 0; k < 4; k++) {
        const int r = k * 16 + j;
        const float sc = (k == 2) ? 1.0f : 0.5f;
        wi[k][0] = w_ih[r * 2 + 0] * sc;
        wi[k][1] = w_ih[r * 2 + 1] * sc;
        wh[k][0] = w_hh[r * 2 + 0] * sc;
        wh[k][1] = w_hh[r * 2 + 1] * sc;
        bb[k]    = (b_ih[r] + b_hh[r]) * sc;
    }
    wr0 = w_hr[j]      * 0.5f;
    wr1 = w_hr[16 + j] * 0.5f;

    const float4* __restrict__ up = (const float4*)u + (size_t)e * T_TOTAL;
    float2* __restrict__ op       = (float2*)out + (size_t)e * T_TOTAL;

    float c = 0.0f, h0 = 0.0f, h1 = 0.0f;

    // ================= teacher-forced phase, unrolled x4 =================
    // No h feedback: gates of all steps independent; only c is serial (8cyc).
#pragma unroll 1
    for (int t = 0; t < N_CTX; t += TU) {
        float4 vv[TU];
#pragma unroll
        for (int s = 0; s < TU; s++) vv[s] = up[t + s];

        // all gates for TU steps (independent FMA block)
        float gg[TU][4];
#pragma unroll
        for (int s = 0; s < TU; s++)
#pragma unroll
            for (int k = 0; k < 4; k++)
                gg[s][k] = fmaf(wi[k][0], vv[s].x,
                           fmaf(wi[k][1], vv[s].y,
                           fmaf(wh[k][0], vv[s].z,
                           fmaf(wh[k][1], vv[s].w, bb[k]))));

        // 16 independent TANHs
        float ti[TU], tf[TU], tg[TU], to[TU];
#pragma unroll
        for (int s = 0; s < TU; s++) {
            ti[s] = tanh_fast(gg[s][0]);
            tf[s] = tanh_fast(gg[s][1]);
            tg[s] = tanh_fast(gg[s][2]);
            to[s] = tanh_fast(gg[s][3]);
        }

        // serial c chain (cheap), tanh(c) off-chain
        float tc[TU];
#pragma unroll
        for (int s = 0; s < TU; s++) {
            float ca = fmaf(tf[s], c, c);            // 2*sigma(f)*c
            float cb = fmaf(ti[s], tg[s], tg[s]);    // 2*sigma(i)*tanh(g)
            c = fmaf(0.5f, ca, 0.5f * cb);
            tc[s] = tanh_fast(c);
        }

        // projections + interleaved shuffle trees (independent across steps)
        float p0[TU], p1[TU];
#pragma unroll
        for (int s = 0; s < TU; s++) {
            float sv = fmaf(to[s], tc[s], tc[s]);    // 2*sigma(o)*tanh(c)
            p0[s] = wr0 * sv;
            p1[s] = wr1 * sv;
        }
#pragma unroll
        for (int k = 1; k < TPE; k <<= 1) {
#pragma unroll
            for (int s = 0; s < TU; s++) {
                p0[s] += __shfl_xor_sync(0xffffffffu, p0[s], k, TPE);
                p1[s] += __shfl_xor_sync(0xffffffffu, p1[s], k, TPE);
            }
        }
        if (j == 0) {
#pragma unroll
            for (int s = 0; s < TU; s++)
                op[t + s] = make_float2(p0[s], p1[s]);
        }
        h0 = p0[TU - 1];
        h1 = p1[TU - 1];
    }

    // ================= recurrent phase (identical to R4) =================
    float4 v = up[N_CTX];
    float xp[4];
#pragma unroll
    for (int k = 0; k < 4; k++)
        xp[k] = fmaf(wi[k][0], v.x, fmaf(wi[k][1], v.y, bb[k]));

#pragma unroll 2
    for (int t = N_CTX; t < T_TOTAL; t++) {
        float4 vn = up[(t + 1 < T_TOTAL) ? (t + 1) : t];
        const float hi0 = h0, hi1 = h1;

        float gi = fmaf(wh[0][0], hi0, fmaf(wh[0][1], hi1, xp[0]));
        float gf = fmaf(wh[1][0], hi0, fmaf(wh[1][1], hi1, xp[1]));
        float gg2 = fmaf(wh[2][0], hi0, fmaf(wh[2][1], hi1, xp[2]));
        float go = fmaf(wh[3][0], hi0, fmaf(wh[3][1], hi1, xp[3]));

        float ti = tanh_fast(gi);
        float tf = tanh_fast(gf);
        float tg = tanh_fast(gg2);
        float to = tanh_fast(go);

        float ca = fmaf(tf, c, c);
        float cb = fmaf(ti, tg, tg);
        c = fmaf(0.5f, ca, 0.5f * cb);

        float tc = tanh_fast(c);
        float s  = fmaf(to, tc, tc);

        float p0 = wr0 * s;
        float p1 = wr1 * s;
#pragma unroll
        for (int k = 1; k < TPE; k <<= 1) {
            p0 += __shfl_xor_sync(0xffffffffu, p0, k, TPE);
            p1 += __shfl_xor_sync(0xffffffffu, p1, k, TPE);
        }
        h0 = p0; h1 = p1;
        if (j == 0) op[t] = make_float2(p0, p1);

#pragma unroll
        for (int k = 0; k < 4; k++)
            xp[k] = fmaf(wi[k][0], vn.x, fmaf(wi[k][1], vn.y, bb[k]));
        v = vn;
    }
}

extern "C" void kernel_launch(void* const* d_in, const int* in_sizes, int n_in,
                              void* d_out, int out_size)
{
    const float* u    = (const float*)d_in[0];
    const float* w_ih = (const float*)d_in[1];
    const float* w_hh = (const float*)d_in[2];
    const float* b_ih = (const float*)d_in[3];
    const float* b_hh = (const float*)d_in[4];
    const float* w_hr = (const float*)d_in[5];
    float* out = (float*)d_out;

    const int B = in_sizes[0] / (T_TOTAL * 4);   // 4096
    const int grid = B / EPB;                    // 1024 blocks x 64 threads

    open_lstm_kernel<<<grid, 64>>>(u, w_ih, w_hh, b_ih, b_hh, w_hr, out);
}